// round 2
// baseline (speedup 1.0000x reference)
#include <cuda_runtime.h>

// Dempster-Shafer combine, algebraically reduced to a pure elementwise map:
//   out = (a1-1)*(a2-1)/C + a1 + a2 - 1          (denom = 1-K cancels exactly)
// HBM-streaming kernel. R2: 2x float4 per thread (MLP_p1=4) + streaming
// cache hints (no reuse -> evict-first loads, streaming stores).

#define INV_C (1.0f / 21.0f)

__device__ __forceinline__ float4 ds_combine4(float4 x, float4 y)
{
    float4 r;
    r.x = fmaf((x.x - 1.0f) * (y.x - 1.0f), INV_C, x.x + y.x - 1.0f);
    r.y = fmaf((x.y - 1.0f) * (y.y - 1.0f), INV_C, x.y + y.y - 1.0f);
    r.z = fmaf((x.z - 1.0f) * (y.z - 1.0f), INV_C, x.z + y.z - 1.0f);
    r.w = fmaf((x.w - 1.0f) * (y.w - 1.0f), INV_C, x.w + y.w - 1.0f);
    return r;
}

__global__ void __launch_bounds__(256)
ds_combine_kernel(const float4* __restrict__ a1,
                  const float4* __restrict__ a2,
                  float4* __restrict__ out,
                  int n4)
{
    // Each block covers 512 consecutive float4s: thread t handles
    // [base + t] and [base + t + 256]. Loads front-batched for MLP.
    int base = blockIdx.x * (blockDim.x * 2) + threadIdx.x;
    int i0 = base;
    int i1 = base + 256;

    if (i1 < n4) {
        // Fast path: all 4 loads issued back-to-back (MLP_p1 = 4).
        float4 x0 = __ldcs(&a1[i0]);
        float4 y0 = __ldcs(&a2[i0]);
        float4 x1 = __ldcs(&a1[i1]);
        float4 y1 = __ldcs(&a2[i1]);
        __stcs(&out[i0], ds_combine4(x0, y0));
        __stcs(&out[i1], ds_combine4(x1, y1));
    } else if (i0 < n4) {
        float4 x0 = __ldcs(&a1[i0]);
        float4 y0 = __ldcs(&a2[i0]);
        __stcs(&out[i0], ds_combine4(x0, y0));
    }
}

extern "C" void kernel_launch(void* const* d_in, const int* in_sizes, int n_in,
                              void* d_out, int out_size)
{
    const float4* a1 = (const float4*)d_in[0];
    const float4* a2 = (const float4*)d_in[1];
    float4* out = (float4*)d_out;

    int n = in_sizes[0];       // 44,040,192 elements (multiple of 4)
    int n4 = n >> 2;           // 11,010,048 float4s

    const int threads = 256;
    const int f4_per_block = threads * 2;                 // 512
    int blocks = (n4 + f4_per_block - 1) / f4_per_block;  // 21504

    ds_combine_kernel<<<blocks, threads>>>(a1, a2, out, n4);
}